// round 2
// baseline (speedup 1.0000x reference)
#include <cuda_runtime.h>

#define NN 50000
#define TT 10
#define EE 1000000
#define HH 8

// Scratch state (no allocations allowed): RNN hidden + per-frame aggregation.
__device__ float g_hidden[NN * HH];
__device__ float g_agg[NN];

typedef unsigned long long u64;

// Packed f32x2 FMA (Blackwell sm_100+). Bit-exact vs two fmaf.
__device__ __forceinline__ u64 fma2(u64 a, u64 b, u64 c) {
    u64 d;
    asm("fma.rn.f32x2 %0, %1, %2, %3;" : "=l"(d) : "l"(a), "l"(b), "l"(c));
    return d;
}
__device__ __forceinline__ u64 pack2(float lo, float hi) {
    u64 d;
    asm("mov.b64 %0, {%1, %2};" : "=l"(d) : "f"(lo), "f"(hi));
    return d;
}
__device__ __forceinline__ void unpack2(u64 v, float& lo, float& hi) {
    asm("mov.b64 {%0, %1}, %2;" : "=f"(lo), "=f"(hi) : "l"(v));
}

__global__ void init_kernel() {
    int i = blockIdx.x * 256 + threadIdx.x;
    if (i < NN * HH) g_hidden[i] = 0.f;
    if (i < NN) g_agg[i] = 0.f;
}

// Per-edge message MLP: feat[9] = [x0[src], hidden[src,0:8]]
//   h1 = relu(feat @ W1 + b1)   (9 -> 32)
//   h2 = relu(h1 @ W2 + b2)     (32 -> 32)
//   msg = sigmoid(h2 @ W3 + b3) * edge_attr
//   agg[dst] += msg
__global__ void __launch_bounds__(256) edge_kernel(
    const float* __restrict__ x, const int* __restrict__ ei,
    const float* __restrict__ ea,
    const float* __restrict__ w1, const float* __restrict__ b1,
    const float* __restrict__ w2, const float* __restrict__ b2,
    const float* __restrict__ w3, const float* __restrict__ b3, int t)
{
    __shared__ __align__(16) float sW1[9 * 32];
    __shared__ __align__(16) float sW2[32 * 32];
    __shared__ __align__(16) float sB1[32];
    __shared__ __align__(16) float sB2[32];
    __shared__ __align__(16) float sW3[32];
    __shared__ float sB3;

    int tid = threadIdx.x;
    for (int i = tid; i < 9 * 32; i += 256) sW1[i] = w1[i];
    for (int i = tid; i < 32 * 32; i += 256) sW2[i] = w2[i];
    if (tid < 32) { sB1[tid] = b1[tid]; sB2[tid] = b2[tid]; sW3[tid] = w3[tid]; }
    if (tid == 0) sB3 = b3[0];
    __syncthreads();

    int e = blockIdx.x * 256 + tid;
    if (e >= EE) return;

    int src = ei[t * EE + e];            // edge_index[0][t][e]
    int dst = ei[TT * EE + t * EE + e];  // edge_index[1][t][e]

    float feat[9];
    feat[0] = __ldg(&x[src * (TT * 2) + t * 2]);   // x[src, t, 0]
    float4 ha = *reinterpret_cast<const float4*>(&g_hidden[src * HH]);
    float4 hb = *reinterpret_cast<const float4*>(&g_hidden[src * HH + 4]);
    feat[1] = ha.x; feat[2] = ha.y; feat[3] = ha.z; feat[4] = ha.w;
    feat[5] = hb.x; feat[6] = hb.y; feat[7] = hb.z; feat[8] = hb.w;
    float eav = __ldg(&ea[e * TT + t]);            // edge_attr[e, t, 0]

    // ---- layer 1: 9 -> 32, f32x2 packed (16 pair-accumulators) ----
    u64 acc[16];
    {
        const u64* pb = reinterpret_cast<const u64*>(sB1);
        #pragma unroll
        for (int j = 0; j < 16; j++) acc[j] = pb[j];
    }
    #pragma unroll
    for (int k = 0; k < 9; k++) {
        u64 aa = pack2(feat[k], feat[k]);
        const u64* wr = reinterpret_cast<const u64*>(&sW1[k * 32]);
        #pragma unroll
        for (int j = 0; j < 16; j++) acc[j] = fma2(aa, wr[j], acc[j]);
    }
    float h1[32];
    #pragma unroll
    for (int j = 0; j < 16; j++) {
        float lo, hi; unpack2(acc[j], lo, hi);
        h1[2 * j]     = fmaxf(lo, 0.f);
        h1[2 * j + 1] = fmaxf(hi, 0.f);
    }

    // ---- layer 2: 32 -> 32 ----
    u64 acc2[16];
    {
        const u64* pb = reinterpret_cast<const u64*>(sB2);
        #pragma unroll
        for (int j = 0; j < 16; j++) acc2[j] = pb[j];
    }
    #pragma unroll
    for (int k = 0; k < 32; k++) {
        u64 aa = pack2(h1[k], h1[k]);
        const u64* wr = reinterpret_cast<const u64*>(&sW2[k * 32]);
        #pragma unroll
        for (int j = 0; j < 16; j++) acc2[j] = fma2(aa, wr[j], acc2[j]);
    }

    // ---- layer 3: 32 -> 1, fused with relu of layer 2 ----
    float s = sB3;
    #pragma unroll
    for (int j = 0; j < 16; j++) {
        float lo, hi; unpack2(acc2[j], lo, hi);
        s += fmaxf(lo, 0.f) * sW3[2 * j] + fmaxf(hi, 0.f) * sW3[2 * j + 1];
    }

    float msg = eav / (1.0f + __expf(-s));
    atomicAdd(&g_agg[dst], msg);
}

// Per-node update + output head:
//   upd_in[10] = [x1[n], hidden[n,0:8], agg[n]]
//   u  = relu(upd_in @ W1 + b1)   (10 -> 32)
//   v  = relu(u @ W2 + b2)        (32 -> 8)
//   hidden_new = tanh(v)
//   o  = relu(hidden_new @ O1 + ob1)  (8 -> 16)
//   out = sigmoid(o @ O2 + ob2)
__global__ void __launch_bounds__(256) node_kernel(
    const float* __restrict__ x,
    const float* __restrict__ w1, const float* __restrict__ b1,
    const float* __restrict__ w2, const float* __restrict__ b2,
    const float* __restrict__ ow1, const float* __restrict__ ob1,
    const float* __restrict__ ow2, const float* __restrict__ ob2,
    float* __restrict__ out, int t)
{
    __shared__ __align__(16) float sW1[10 * 32];
    __shared__ __align__(16) float sW2[32 * 8];
    __shared__ __align__(16) float sO1[8 * 16];
    __shared__ __align__(16) float sB1[32];
    __shared__ __align__(16) float sB2[8];
    __shared__ __align__(16) float sOB1[16];
    __shared__ __align__(16) float sO2[16];
    __shared__ float sOB2;

    int tid = threadIdx.x;
    for (int i = tid; i < 320; i += 256) sW1[i] = w1[i];
    if (tid < 256) sW2[tid] = w2[tid];
    if (tid < 128) sO1[tid] = ow1[tid];
    if (tid < 32) sB1[tid] = b1[tid];
    if (tid < 8)  sB2[tid] = b2[tid];
    if (tid < 16) { sOB1[tid] = ob1[tid]; sO2[tid] = ow2[tid]; }
    if (tid == 0) sOB2 = ob2[0];
    __syncthreads();

    int n = blockIdx.x * 256 + tid;
    if (n >= NN) return;

    float in[10];
    in[0] = x[n * (TT * 2) + t * 2 + 1];  // x[n, t, 1]
    float4 ha = *reinterpret_cast<const float4*>(&g_hidden[n * HH]);
    float4 hb = *reinterpret_cast<const float4*>(&g_hidden[n * HH + 4]);
    in[1] = ha.x; in[2] = ha.y; in[3] = ha.z; in[4] = ha.w;
    in[5] = hb.x; in[6] = hb.y; in[7] = hb.z; in[8] = hb.w;
    in[9] = g_agg[n];
    g_agg[n] = 0.f;  // ready for next frame

    float u[32];
    #pragma unroll
    for (int j = 0; j < 32; j++) u[j] = sB1[j];
    #pragma unroll
    for (int k = 0; k < 10; k++) {
        float a = in[k];
        #pragma unroll
        for (int j = 0; j < 32; j++) u[j] += a * sW1[k * 32 + j];
    }
    #pragma unroll
    for (int j = 0; j < 32; j++) u[j] = fmaxf(u[j], 0.f);

    float v[8];
    #pragma unroll
    for (int j = 0; j < 8; j++) v[j] = sB2[j];
    #pragma unroll
    for (int k = 0; k < 32; k++) {
        float a = u[k];
        #pragma unroll
        for (int j = 0; j < 8; j++) v[j] += a * sW2[k * 8 + j];
    }

    float h[8];
    #pragma unroll
    for (int j = 0; j < 8; j++) h[j] = tanhf(fmaxf(v[j], 0.f));

    *reinterpret_cast<float4*>(&g_hidden[n * HH])     = make_float4(h[0], h[1], h[2], h[3]);
    *reinterpret_cast<float4*>(&g_hidden[n * HH + 4]) = make_float4(h[4], h[5], h[6], h[7]);

    float o[16];
    #pragma unroll
    for (int j = 0; j < 16; j++) o[j] = sOB1[j];
    #pragma unroll
    for (int k = 0; k < 8; k++) {
        float a = h[k];
        #pragma unroll
        for (int j = 0; j < 16; j++) o[j] += a * sO1[k * 16 + j];
    }
    float s = sOB2;
    #pragma unroll
    for (int j = 0; j < 16; j++) s += fmaxf(o[j], 0.f) * sO2[j];

    out[t * NN + n] = 1.0f / (1.0f + __expf(-s));
}

extern "C" void kernel_launch(void* const* d_in, const int* in_sizes, int n_in,
                              void* d_out, int out_size) {
    (void)in_sizes; (void)n_in; (void)out_size;
    const float* x     = (const float*)d_in[0];
    const int*   ei    = (const int*)  d_in[1];
    const float* ea    = (const float*)d_in[2];
    const float* m1w1  = (const float*)d_in[3];
    const float* m1b1  = (const float*)d_in[4];
    const float* m1w2  = (const float*)d_in[5];
    const float* m1b2  = (const float*)d_in[6];
    const float* m1w3  = (const float*)d_in[7];
    const float* m1b3  = (const float*)d_in[8];
    const float* m2w1  = (const float*)d_in[9];
    const float* m2b1  = (const float*)d_in[10];
    const float* m2w2  = (const float*)d_in[11];
    const float* m2b2  = (const float*)d_in[12];
    const float* ow1   = (const float*)d_in[13];
    const float* ob1   = (const float*)d_in[14];
    const float* ow2   = (const float*)d_in[15];
    const float* ob2   = (const float*)d_in[16];
    float* out = (float*)d_out;

    init_kernel<<<(NN * HH + 255) / 256, 256>>>();

    for (int t = 0; t < TT; t++) {
        edge_kernel<<<(EE + 255) / 256, 256>>>(
            x, ei, ea, m1w1, m1b1, m1w2, m1b2, m1w3, m1b3, t);
        node_kernel<<<(NN + 255) / 256, 256>>>(
            x, m2w1, m2b1, m2w2, m2b2, ow1, ob1, ow2, ob2, out, t);
    }
}

// round 4
// speedup vs baseline: 3.6526x; 3.6526x over previous
#include <cuda_runtime.h>

#define NN 50000
#define TT 10
#define EE 1000000
#define HH 8

// Scratch (no allocations allowed): RNN state + per-frame agg + per-node msg + transposed edge_attr.
__device__ float g_hidden[NN * HH];
__device__ float g_agg[NN];
__device__ float g_p[NN];
__device__ __align__(16) float g_ea_t[TT * EE];   // [T][E] transposed edge_attr (40 MB)

typedef unsigned long long u64;

// Packed f32x2 FMA (Blackwell sm_100+). Bit-exact vs two fmaf.
__device__ __forceinline__ u64 fma2(u64 a, u64 b, u64 c) {
    u64 d;
    asm("fma.rn.f32x2 %0, %1, %2, %3;" : "=l"(d) : "l"(a), "l"(b), "l"(c));
    return d;
}
__device__ __forceinline__ u64 pack2(float lo, float hi) {
    u64 d;
    asm("mov.b64 %0, {%1, %2};" : "=l"(d) : "f"(lo), "f"(hi));
    return d;
}
__device__ __forceinline__ void unpack2(u64 v, float& lo, float& hi) {
    asm("mov.b64 {%0, %1}, %2;" : "=f"(lo), "=f"(hi) : "l"(v));
}

__global__ void init_kernel() {
    int i = blockIdx.x * 256 + threadIdx.x;
    if (i < NN * HH) g_hidden[i] = 0.f;
    if (i < NN) g_agg[i] = 0.f;
}

// One-time transpose: ea[e, t, 0] (stride-T) -> g_ea_t[t * EE + e] (coalesced per frame).
__global__ void __launch_bounds__(256) transpose_ea_kernel(const float* __restrict__ ea) {
    int e = blockIdx.x * 256 + threadIdx.x;
    if (e >= EE) return;
    float v[TT];
    #pragma unroll
    for (int k = 0; k < TT; k++) v[k] = ea[e * TT + k];
    #pragma unroll
    for (int k = 0; k < TT; k++) g_ea_t[k * EE + e] = v[k];
}

// Per-node message scalar: p = sigmoid(mlp1([x0, hidden])), mlp1 = 9->32->32->1.
__device__ __forceinline__ float compute_p(
    const float* feat,  // [9]
    const float* sW1, const float* sB1,
    const float* sW2, const float* sB2,
    const float* sW3, float b3)
{
    // layer 1: 9 -> 32 (f32x2 packed)
    u64 acc[16];
    {
        const u64* pb = reinterpret_cast<const u64*>(sB1);
        #pragma unroll
        for (int j = 0; j < 16; j++) acc[j] = pb[j];
    }
    #pragma unroll
    for (int k = 0; k < 9; k++) {
        u64 aa = pack2(feat[k], feat[k]);
        const u64* wr = reinterpret_cast<const u64*>(&sW1[k * 32]);
        #pragma unroll
        for (int j = 0; j < 16; j++) acc[j] = fma2(aa, wr[j], acc[j]);
    }
    float h1[32];
    #pragma unroll
    for (int j = 0; j < 16; j++) {
        float lo, hi; unpack2(acc[j], lo, hi);
        h1[2 * j]     = fmaxf(lo, 0.f);
        h1[2 * j + 1] = fmaxf(hi, 0.f);
    }
    // layer 2: 32 -> 32
    u64 acc2[16];
    {
        const u64* pb = reinterpret_cast<const u64*>(sB2);
        #pragma unroll
        for (int j = 0; j < 16; j++) acc2[j] = pb[j];
    }
    #pragma unroll
    for (int k = 0; k < 32; k++) {
        u64 aa = pack2(h1[k], h1[k]);
        const u64* wr = reinterpret_cast<const u64*>(&sW2[k * 32]);
        #pragma unroll
        for (int j = 0; j < 16; j++) acc2[j] = fma2(aa, wr[j], acc2[j]);
    }
    // layer 3: 32 -> 1 (relu fused)
    float s = b3;
    #pragma unroll
    for (int j = 0; j < 16; j++) {
        float lo, hi; unpack2(acc2[j], lo, hi);
        s += fmaxf(lo, 0.f) * sW3[2 * j] + fmaxf(hi, 0.f) * sW3[2 * j + 1];
    }
    return 1.0f / (1.0f + __expf(-s));
}

// Frame-0 message kernel: p[n] for t=0 from the zero-initialized hidden.
__global__ void __launch_bounds__(256) msg_kernel(
    const float* __restrict__ x,
    const float* __restrict__ w1, const float* __restrict__ b1,
    const float* __restrict__ w2, const float* __restrict__ b2,
    const float* __restrict__ w3, const float* __restrict__ b3, int t)
{
    __shared__ __align__(16) float sW1[9 * 32];
    __shared__ __align__(16) float sW2[32 * 32];
    __shared__ __align__(16) float sB1[32];
    __shared__ __align__(16) float sB2[32];
    __shared__ __align__(16) float sW3[32];
    __shared__ float sB3;

    int tid = threadIdx.x;
    for (int i = tid; i < 9 * 32; i += 256) sW1[i] = w1[i];
    for (int i = tid; i < 32 * 32; i += 256) sW2[i] = w2[i];
    if (tid < 32) { sB1[tid] = b1[tid]; sB2[tid] = b2[tid]; sW3[tid] = w3[tid]; }
    if (tid == 0) sB3 = b3[0];
    __syncthreads();

    int n = blockIdx.x * 256 + tid;
    if (n >= NN) return;

    float feat[9];
    feat[0] = x[n * (TT * 2) + t * 2];  // x[n, t, 0]
    float4 ha = *reinterpret_cast<const float4*>(&g_hidden[n * HH]);
    float4 hb = *reinterpret_cast<const float4*>(&g_hidden[n * HH + 4]);
    feat[1] = ha.x; feat[2] = ha.y; feat[3] = ha.z; feat[4] = ha.w;
    feat[5] = hb.x; feat[6] = hb.y; feat[7] = hb.z; feat[8] = hb.w;

    g_p[n] = compute_p(feat, sW1, sB1, sW2, sB2, sW3, sB3);
}

// Pure scatter: agg[dst] += p[src] * ea_t[e], 4 edges per thread.
__global__ void __launch_bounds__(256) edge_kernel(const int* __restrict__ ei, int t)
{
    int idx = blockIdx.x * 256 + threadIdx.x;
    if (idx >= EE / 4) return;
    int i = idx * 4;

    int4 s4 = *reinterpret_cast<const int4*>(&ei[t * EE + i]);
    int4 d4 = *reinterpret_cast<const int4*>(&ei[TT * EE + t * EE + i]);
    float4 a4 = *reinterpret_cast<const float4*>(&g_ea_t[t * EE + i]);

    float p0 = __ldg(&g_p[s4.x]);
    float p1 = __ldg(&g_p[s4.y]);
    float p2 = __ldg(&g_p[s4.z]);
    float p3 = __ldg(&g_p[s4.w]);

    atomicAdd(&g_agg[d4.x], p0 * a4.x);
    atomicAdd(&g_agg[d4.y], p1 * a4.y);
    atomicAdd(&g_agg[d4.z], p2 * a4.z);
    atomicAdd(&g_agg[d4.w], p3 * a4.w);
}

// Fused per-node: hidden update + output for frame t, then p for frame t+1.
__global__ void __launch_bounds__(256) update_msg_kernel(
    const float* __restrict__ x,
    const float* __restrict__ w1, const float* __restrict__ b1,
    const float* __restrict__ w2, const float* __restrict__ b2,
    const float* __restrict__ ow1, const float* __restrict__ ob1,
    const float* __restrict__ ow2, const float* __restrict__ ob2,
    const float* __restrict__ mw1, const float* __restrict__ mb1,
    const float* __restrict__ mw2, const float* __restrict__ mb2,
    const float* __restrict__ mw3, const float* __restrict__ mb3,
    float* __restrict__ out, int t)
{
    __shared__ __align__(16) float sW1[10 * 32];
    __shared__ __align__(16) float sW2[32 * 8];
    __shared__ __align__(16) float sO1[8 * 16];
    __shared__ __align__(16) float sB1[32];
    __shared__ __align__(16) float sB2[8];
    __shared__ __align__(16) float sOB1[16];
    __shared__ __align__(16) float sO2[16];
    __shared__ float sOB2;
    // mlp1 weights for next-frame p
    __shared__ __align__(16) float sMW1[9 * 32];
    __shared__ __align__(16) float sMW2[32 * 32];
    __shared__ __align__(16) float sMB1[32];
    __shared__ __align__(16) float sMB2[32];
    __shared__ __align__(16) float sMW3[32];
    __shared__ float sMB3;

    int tid = threadIdx.x;
    for (int i = tid; i < 320; i += 256) sW1[i] = w1[i];
    if (tid < 256) sW2[tid] = w2[tid];
    if (tid < 128) sO1[tid] = ow1[tid];
    if (tid < 32) sB1[tid] = b1[tid];
    if (tid < 8)  sB2[tid] = b2[tid];
    if (tid < 16) { sOB1[tid] = ob1[tid]; sO2[tid] = ow2[tid]; }
    if (tid == 0) { sOB2 = ob2[0]; sMB3 = mb3[0]; }
    for (int i = tid; i < 9 * 32; i += 256) sMW1[i] = mw1[i];
    for (int i = tid; i < 32 * 32; i += 256) sMW2[i] = mw2[i];
    if (tid < 32) { sMB1[tid] = mb1[tid]; sMB2[tid] = mb2[tid]; sMW3[tid] = mw3[tid]; }
    __syncthreads();

    int n = blockIdx.x * 256 + tid;
    if (n >= NN) return;

    float in[10];
    in[0] = x[n * (TT * 2) + t * 2 + 1];  // x[n, t, 1]
    float4 ha = *reinterpret_cast<const float4*>(&g_hidden[n * HH]);
    float4 hb = *reinterpret_cast<const float4*>(&g_hidden[n * HH + 4]);
    in[1] = ha.x; in[2] = ha.y; in[3] = ha.z; in[4] = ha.w;
    in[5] = hb.x; in[6] = hb.y; in[7] = hb.z; in[8] = hb.w;
    in[9] = g_agg[n];
    g_agg[n] = 0.f;  // reset for next frame

    float u[32];
    #pragma unroll
    for (int j = 0; j < 32; j++) u[j] = sB1[j];
    #pragma unroll
    for (int k = 0; k < 10; k++) {
        float a = in[k];
        #pragma unroll
        for (int j = 0; j < 32; j++) u[j] += a * sW1[k * 32 + j];
    }
    #pragma unroll
    for (int j = 0; j < 32; j++) u[j] = fmaxf(u[j], 0.f);

    float v[8];
    #pragma unroll
    for (int j = 0; j < 8; j++) v[j] = sB2[j];
    #pragma unroll
    for (int k = 0; k < 32; k++) {
        float a = u[k];
        #pragma unroll
        for (int j = 0; j < 8; j++) v[j] += a * sW2[k * 8 + j];
    }

    float h[8];
    #pragma unroll
    for (int j = 0; j < 8; j++) h[j] = tanhf(fmaxf(v[j], 0.f));

    *reinterpret_cast<float4*>(&g_hidden[n * HH])     = make_float4(h[0], h[1], h[2], h[3]);
    *reinterpret_cast<float4*>(&g_hidden[n * HH + 4]) = make_float4(h[4], h[5], h[6], h[7]);

    float o[16];
    #pragma unroll
    for (int j = 0; j < 16; j++) o[j] = sOB1[j];
    #pragma unroll
    for (int k = 0; k < 8; k++) {
        float a = h[k];
        #pragma unroll
        for (int j = 0; j < 16; j++) o[j] += a * sO1[k * 16 + j];
    }
    float s = sOB2;
    #pragma unroll
    for (int j = 0; j < 16; j++) s += fmaxf(o[j], 0.f) * sO2[j];

    out[t * NN + n] = 1.0f / (1.0f + __expf(-s));

    // next-frame message scalar
    if (t + 1 < TT) {
        float feat[9];
        feat[0] = x[n * (TT * 2) + (t + 1) * 2];  // x[n, t+1, 0]
        #pragma unroll
        for (int j = 0; j < 8; j++) feat[1 + j] = h[j];
        g_p[n] = compute_p(feat, sMW1, sMB1, sMW2, sMB2, sMW3, sMB3);
    }
}

extern "C" void kernel_launch(void* const* d_in, const int* in_sizes, int n_in,
                              void* d_out, int out_size) {
    (void)in_sizes; (void)n_in; (void)out_size;
    const float* x     = (const float*)d_in[0];
    const int*   ei    = (const int*)  d_in[1];
    const float* ea    = (const float*)d_in[2];
    const float* m1w1  = (const float*)d_in[3];
    const float* m1b1  = (const float*)d_in[4];
    const float* m1w2  = (const float*)d_in[5];
    const float* m1b2  = (const float*)d_in[6];
    const float* m1w3  = (const float*)d_in[7];
    const float* m1b3  = (const float*)d_in[8];
    const float* m2w1  = (const float*)d_in[9];
    const float* m2b1  = (const float*)d_in[10];
    const float* m2w2  = (const float*)d_in[11];
    const float* m2b2  = (const float*)d_in[12];
    const float* ow1   = (const float*)d_in[13];
    const float* ob1   = (const float*)d_in[14];
    const float* ow2   = (const float*)d_in[15];
    const float* ob2   = (const float*)d_in[16];
    float* out = (float*)d_out;

    init_kernel<<<(NN * HH + 255) / 256, 256>>>();
    transpose_ea_kernel<<<(EE + 255) / 256, 256>>>(ea);
    msg_kernel<<<(NN + 255) / 256, 256>>>(x, m1w1, m1b1, m1w2, m1b2, m1w3, m1b3, 0);

    for (int t = 0; t < TT; t++) {
        edge_kernel<<<(EE / 4 + 255) / 256, 256>>>(ei, t);
        update_msg_kernel<<<(NN + 255) / 256, 256>>>(
            x, m2w1, m2b1, m2w2, m2b2, ow1, ob1, ow2, ob2,
            m1w1, m1b1, m1w2, m1b2, m1w3, m1b3, out, t);
    }
}